// round 11
// baseline (speedup 1.0000x reference)
#include <cuda_runtime.h>
#include <math.h>

#define ROW 85          // 5 + NUM_CLASSES
#define NCLS 80
#define NT 256
#define UNROLL 8
#define WPB (NT / 32)   // warps per block
#define LOG_CLAMP -100.0f
#define KEEP_NUM 90     // percent of cells pinned in L2 (94MB lines < 126MB cap)

// global accumulators: [0]=xy [1]=wh [2]=cls [3]=n [4]=conf_corr [5]=conf_base
__device__ float g_acc[6];
__device__ unsigned int g_done;

__device__ __forceinline__ float sigm(float x) {
    return 1.0f / (1.0f + expf(-x));
}
__device__ __forceinline__ unsigned long long pol_keep() {
    unsigned long long pol;
    asm("createpolicy.fractional.L2::evict_last.b64 %0, 1.0;" : "=l"(pol));
    return pol;
}
__device__ __forceinline__ unsigned long long pol_stream() {
    unsigned long long pol;
    asm("createpolicy.fractional.L2::evict_first.b64 %0, 1.0;" : "=l"(pol));
    return pol;
}
__device__ __forceinline__ float ldg_pol(const float* p, unsigned long long pol) {
    float v;
    asm("ld.global.L2::cache_hint.f32 %0, [%1], %2;"
        : "=f"(v) : "l"(p), "l"(pol));
    return v;
}
// softplus(x) = -max(log(sigmoid(-x)), -100)  (matches reference BCE clamping)
// fast even-Taylor path for |x| <= 1 (abs err < 5e-7), exact fallback otherwise
__device__ __forceinline__ float softplus_c(float x) {
    if (fabsf(x) <= 1.0f) {
        float u = x * x;
        float p = 0.125f + u * (-5.2083333e-3f + u * 3.4722222e-4f);
        return 0.69314718056f + 0.5f * x + u * p;
    }
    float s = 1.0f / (1.0f + expf(x));   // sigmoid(-x)
    return -fmaxf(logf(s), LOG_CLAMP);
}
// decode H/W whether stored as int32 or float32 bits
__device__ __forceinline__ int decode_dim(const int* p) {
    int raw = p[0];
    if (raw >= (1 << 20) || raw < 0) return (int)__int_as_float(raw);
    return raw;
}

__device__ __forceinline__ void target_cell(const float* tg, float fW, float fH,
                                            int W, bool& valid, int& gi) {
    float cid = tg[0], cx = tg[1], cy = tg[2], w = tg[3], h = tg[4];
    bool fin = isfinite(cid) && isfinite(cx) && isfinite(cy) &&
               isfinite(w) && isfinite(h);
    float gx = floorf(cx * fW);
    float gy = floorf(cy * fH);
    valid = fin && (gx >= 0.0f) && (gx < fW) && (gy >= 0.0f) && (gy < fH);
    float gxc = fminf(fmaxf(gx, 0.0f), fW - 1.0f);
    float gyc = fminf(fmaxf(gy, 0.0f), fH - 1.0f);
    if (!(gxc == gxc)) gxc = 0.0f;
    if (!(gyc == gyc)) gyc = 0.0f;
    gi = (int)gyc * W + (int)gxc;
}

__global__ void loss_kernel(const float* __restrict__ pred,
                            const float* __restrict__ tgt,
                            const int* __restrict__ Hp,
                            const int* __restrict__ Wp,
                            long n_cells, int ntg, int dense_nb,
                            float* __restrict__ out, int out_size) {
    __shared__ float sh[NT];
    const unsigned long long pkeep = pol_keep();
    const unsigned long long pstream = pol_stream();
    const long keepN = n_cells * KEEP_NUM / 100;

    if (blockIdx.x < (unsigned)dense_nb) {
        // ---- dense conf base: 8 front-batched independent loads, no loop ----
        const long TOT = (long)dense_nb * NT;
        const long nm1 = n_cells - 1;
        const long base = (long)blockIdx.x * NT + threadIdx.x;
        float x[UNROLL];
        #pragma unroll
        for (int k = 0; k < UNROLL; k++) {
            long j = base + (long)k * TOT;
            long c = j <= nm1 ? j : nm1;
            x[k] = ldg_pol(&pred[c * ROW + 4], c < keepN ? pkeep : pstream);
        }
        float acc = 0.0f;
        #pragma unroll
        for (int k = 0; k < UNROLL; k++) {
            long j = base + (long)k * TOT;
            if (j <= nm1) acc += softplus_c(x[k]);
        }
        sh[threadIdx.x] = acc;
        __syncthreads();
        for (int o = NT / 2; o > 0; o >>= 1) {
            if (threadIdx.x < o) sh[threadIdx.x] += sh[threadIdx.x + o];
            __syncthreads();
        }
        if (threadIdx.x == 0) atomicAdd(&g_acc[5], sh[0]);
    } else {
        // ---- warp-per-target ----
        const int wid = threadIdx.x >> 5;
        const int lid = threadIdx.x & 31;
        const int t = (blockIdx.x - dense_nb) * WPB + wid;
        if (t < ntg) {
            const int H = decode_dim(Hp);
            const int W = decode_dim(Wp);
            const long HW = (long)H * (long)W;
            const int B = (int)(n_cells / HW);
            const int T = ntg / B;
            const int b = t / T;
            const int tloc = t - b * T;
            const float fW = (float)W, fH = (float)H;

            const float* bt = tgt + (long)b * T * 5;
            const float* tg = bt + tloc * 5;
            bool valid;
            int gi;
            target_cell(tg, fW, fH, W, valid, gi);
            const float* p = pred + ((long)b * HW + gi) * ROW;

            // class BCE across lanes (c = lid, lid+32, lid+64)
            float v = 0.0f;
            if (valid) {
                int cid = (int)tg[0];
                for (int c = lid; c < NCLS; c += 32) {
                    float lg = ldg_pol(&p[5 + c], pkeep);
                    v += softplus_c((c == cid) ? -lg : lg);
                }
            }
            #pragma unroll
            for (int o = 16; o > 0; o >>= 1)
                v += __shfl_xor_sync(0xffffffffu, v, o);

            // duplicate-cell scan parallel across lanes
            bool dup = false;
            for (int u = lid; u < tloc; u += 32) {
                bool vu; int gu;
                target_cell(bt + u * 5, fW, fH, W, vu, gu);
                if (vu && gu == gi) dup = true;
            }
            bool anydup = __any_sync(0xffffffffu, dup);

            if (lid == 0 && valid) {
                float cxW = tg[1] * fW, cyH = tg[2] * fH;
                float tx = cxW - floorf(cxW);
                float ty = cyH - floorf(cyH);
                float px = sigm(p[0]);
                float py = sigm(p[1]);
                float xy = 0.5f * ((px - tx) * (px - tx) + (py - ty) * (py - ty));

                float pw = expf(p[2]);
                float ph = expf(p[3]);
                float tw = tg[3] * fW, th = tg[4] * fH;
                float wh = 0.5f * ((pw - tw) * (pw - tw) + (ph - th) * (ph - th));

                atomicAdd(&g_acc[0], xy);
                atomicAdd(&g_acc[1], wh);
                atomicAdd(&g_acc[2], v * (1.0f / (float)NCLS));
                atomicAdd(&g_acc[3], 1.0f);
                if (!anydup) {
                    float c = p[4];
                    float cf = softplus_c(-c) - softplus_c(c);
                    atomicAdd(&g_acc[4], cf);
                }
            }
        }
    }

    // ---- last-block finish ----
    __syncthreads();
    if (threadIdx.x == 0) {
        __threadfence();
        unsigned int ticket = atomicAdd(&g_done, 1u);
        if (ticket == gridDim.x - 1) {
            __threadfence();
            float xyS = g_acc[0], whS = g_acc[1], clsS = g_acc[2];
            float nS = g_acc[3], cfS = g_acc[4], baseS = g_acc[5];
            float denom = fmaxf(nS, 1.0f);
            float loss_xy = xyS / denom;
            float loss_wh = whS / denom;
            float loss_cls = clsS / denom;
            float loss_conf = (baseS + cfS) / (float)n_cells;
            float total = loss_xy * 5.0f + loss_wh * 5.0f + loss_conf + loss_cls;
            out[0] = total;
            out[1] = loss_xy;
            out[2] = loss_wh;
            out[3] = loss_conf;
            out[4] = loss_cls;
            for (int i = 5; i < out_size; i++) out[i] = 0.0f;
            // reset for the next graph replay
            for (int k = 0; k < 6; k++) g_acc[k] = 0.0f;
            __threadfence();
            g_done = 0u;
        }
    }
}

extern "C" void kernel_launch(void* const* d_in, const int* in_sizes, int n_in,
                              void* d_out, int out_size) {
    const float* pred = (const float*)d_in[0];
    const float* tgt  = (const float*)d_in[1];
    const int* Hp = (const int*)d_in[2];
    const int* Wp = (const int*)d_in[3];
    long n_pred = in_sizes[0];
    long n_tgt  = in_sizes[1];
    long n_cells = n_pred / ROW;
    int ntg = (int)(n_tgt / 5);

    int dense_nb = (int)((n_cells + (long)NT * UNROLL - 1) / ((long)NT * UNROLL));
    int tgt_nb = (ntg + WPB - 1) / WPB;

    loss_kernel<<<dense_nb + tgt_nb, NT>>>(pred, tgt, Hp, Wp, n_cells, ntg,
                                           dense_nb, (float*)d_out, out_size);
}

// round 12
// speedup vs baseline: 1.1224x; 1.1224x over previous
#include <cuda_runtime.h>
#include <math.h>

#define ROW 85          // 5 + NUM_CLASSES
#define NCLS 80
#define NT 256
#define UNROLL 16
#define WPB (NT / 32)   // warps per block
#define LOG_CLAMP -100.0f
#define KEEP_NUM 55     // percent of cells pinned in L2 (evict_last way-cap ~ half)

// global accumulators: [0]=xy [1]=wh [2]=cls [3]=n [4]=conf_corr [5]=conf_base
__device__ float g_acc[6];
__device__ unsigned int g_done;

__device__ __forceinline__ float sigm(float x) {
    return 1.0f / (1.0f + expf(-x));
}
__device__ __forceinline__ unsigned long long pol_keep() {
    unsigned long long pol;
    asm("createpolicy.fractional.L2::evict_last.b64 %0, 1.0;" : "=l"(pol));
    return pol;
}
__device__ __forceinline__ unsigned long long pol_stream() {
    unsigned long long pol;
    asm("createpolicy.fractional.L2::evict_first.b64 %0, 1.0;" : "=l"(pol));
    return pol;
}
__device__ __forceinline__ float ldg_pol(const float* p, unsigned long long pol) {
    float v;
    asm("ld.global.L2::cache_hint.f32 %0, [%1], %2;"
        : "=f"(v) : "l"(p), "l"(pol));
    return v;
}
// softplus(x) = -max(log(sigmoid(-x)), -100)  (matches reference BCE clamping)
// fast even-Taylor path for |x| <= 1 (abs err < 5e-7), exact fallback otherwise
__device__ __forceinline__ float softplus_c(float x) {
    if (fabsf(x) <= 1.0f) {
        float u = x * x;
        float p = 0.125f + u * (-5.2083333e-3f + u * 3.4722222e-4f);
        return 0.69314718056f + 0.5f * x + u * p;
    }
    float s = 1.0f / (1.0f + expf(x));   // sigmoid(-x)
    return -fmaxf(logf(s), LOG_CLAMP);
}
// decode H/W whether stored as int32 or float32 bits
__device__ __forceinline__ int decode_dim(const int* p) {
    int raw = p[0];
    if (raw >= (1 << 20) || raw < 0) return (int)__int_as_float(raw);
    return raw;
}

__device__ __forceinline__ void target_cell(const float* tg, float fW, float fH,
                                            int W, bool& valid, int& gi) {
    float cid = tg[0], cx = tg[1], cy = tg[2], w = tg[3], h = tg[4];
    bool fin = isfinite(cid) && isfinite(cx) && isfinite(cy) &&
               isfinite(w) && isfinite(h);
    float gx = floorf(cx * fW);
    float gy = floorf(cy * fH);
    valid = fin && (gx >= 0.0f) && (gx < fW) && (gy >= 0.0f) && (gy < fH);
    float gxc = fminf(fmaxf(gx, 0.0f), fW - 1.0f);
    float gyc = fminf(fmaxf(gy, 0.0f), fH - 1.0f);
    if (!(gxc == gxc)) gxc = 0.0f;
    if (!(gyc == gyc)) gyc = 0.0f;
    gi = (int)gyc * W + (int)gxc;
}

__global__ void loss_kernel(const float* __restrict__ pred,
                            const float* __restrict__ tgt,
                            const int* __restrict__ Hp,
                            const int* __restrict__ Wp,
                            long n_cells, int ntg, int dense_nb,
                            float* __restrict__ out, int out_size) {
    __shared__ float sh[NT];
    const unsigned long long pkeep = pol_keep();
    const unsigned long long pstream = pol_stream();

    if (blockIdx.x < (unsigned)dense_nb) {
        // ---- dense conf base: 16 front-batched independent loads, no loop ----
        // 32-bit indexing (n_cells*ROW < 2^31) shortens the address chains so
        // the 16 LDGs issue back-to-back.
        const unsigned int N = (unsigned int)n_cells;
        const unsigned int TOT = (unsigned int)dense_nb * NT;
        const unsigned int nm1 = N - 1;
        const unsigned int keepN = (unsigned int)(N * (unsigned long)KEEP_NUM / 100);
        const unsigned int base = blockIdx.x * NT + threadIdx.x;
        float x[UNROLL];
        #pragma unroll
        for (int k = 0; k < UNROLL; k++) {
            unsigned int j = base + (unsigned int)k * TOT;
            unsigned int c = j <= nm1 ? j : nm1;
            x[k] = ldg_pol(&pred[(unsigned int)(c * ROW + 4)],
                           c < keepN ? pkeep : pstream);
        }
        float acc = 0.0f;
        #pragma unroll
        for (int k = 0; k < UNROLL; k++) {
            unsigned int j = base + (unsigned int)k * TOT;
            if (j <= nm1) acc += softplus_c(x[k]);
        }
        sh[threadIdx.x] = acc;
        __syncthreads();
        for (int o = NT / 2; o > 0; o >>= 1) {
            if (threadIdx.x < o) sh[threadIdx.x] += sh[threadIdx.x + o];
            __syncthreads();
        }
        if (threadIdx.x == 0) atomicAdd(&g_acc[5], sh[0]);
    } else {
        // ---- warp-per-target ----
        const int wid = threadIdx.x >> 5;
        const int lid = threadIdx.x & 31;
        const int t = (blockIdx.x - dense_nb) * WPB + wid;
        if (t < ntg) {
            const int H = decode_dim(Hp);
            const int W = decode_dim(Wp);
            const long HW = (long)H * (long)W;
            const int B = (int)(n_cells / HW);
            const int T = ntg / B;
            const int b = t / T;
            const int tloc = t - b * T;
            const float fW = (float)W, fH = (float)H;

            const float* bt = tgt + (long)b * T * 5;
            const float* tg = bt + tloc * 5;
            bool valid;
            int gi;
            target_cell(tg, fW, fH, W, valid, gi);
            const float* p = pred + ((long)b * HW + gi) * ROW;

            // class BCE across lanes (c = lid, lid+32, lid+64)
            float v = 0.0f;
            if (valid) {
                int cid = (int)tg[0];
                for (int c = lid; c < NCLS; c += 32) {
                    float lg = ldg_pol(&p[5 + c], pkeep);
                    v += softplus_c((c == cid) ? -lg : lg);
                }
            }
            #pragma unroll
            for (int o = 16; o > 0; o >>= 1)
                v += __shfl_xor_sync(0xffffffffu, v, o);

            // duplicate-cell scan parallel across lanes
            bool dup = false;
            for (int u = lid; u < tloc; u += 32) {
                bool vu; int gu;
                target_cell(bt + u * 5, fW, fH, W, vu, gu);
                if (vu && gu == gi) dup = true;
            }
            bool anydup = __any_sync(0xffffffffu, dup);

            if (lid == 0 && valid) {
                float cxW = tg[1] * fW, cyH = tg[2] * fH;
                float tx = cxW - floorf(cxW);
                float ty = cyH - floorf(cyH);
                float px = sigm(p[0]);
                float py = sigm(p[1]);
                float xy = 0.5f * ((px - tx) * (px - tx) + (py - ty) * (py - ty));

                float pw = expf(p[2]);
                float ph = expf(p[3]);
                float tw = tg[3] * fW, th = tg[4] * fH;
                float wh = 0.5f * ((pw - tw) * (pw - tw) + (ph - th) * (ph - th));

                atomicAdd(&g_acc[0], xy);
                atomicAdd(&g_acc[1], wh);
                atomicAdd(&g_acc[2], v * (1.0f / (float)NCLS));
                atomicAdd(&g_acc[3], 1.0f);
                if (!anydup) {
                    float c = p[4];
                    float cf = softplus_c(-c) - softplus_c(c);
                    atomicAdd(&g_acc[4], cf);
                }
            }
        }
    }

    // ---- last-block finish ----
    __syncthreads();
    if (threadIdx.x == 0) {
        __threadfence();
        unsigned int ticket = atomicAdd(&g_done, 1u);
        if (ticket == gridDim.x - 1) {
            __threadfence();
            float xyS = g_acc[0], whS = g_acc[1], clsS = g_acc[2];
            float nS = g_acc[3], cfS = g_acc[4], baseS = g_acc[5];
            float denom = fmaxf(nS, 1.0f);
            float loss_xy = xyS / denom;
            float loss_wh = whS / denom;
            float loss_cls = clsS / denom;
            float loss_conf = (baseS + cfS) / (float)n_cells;
            float total = loss_xy * 5.0f + loss_wh * 5.0f + loss_conf + loss_cls;
            out[0] = total;
            out[1] = loss_xy;
            out[2] = loss_wh;
            out[3] = loss_conf;
            out[4] = loss_cls;
            for (int i = 5; i < out_size; i++) out[i] = 0.0f;
            // reset for the next graph replay
            for (int k = 0; k < 6; k++) g_acc[k] = 0.0f;
            __threadfence();
            g_done = 0u;
        }
    }
}

extern "C" void kernel_launch(void* const* d_in, const int* in_sizes, int n_in,
                              void* d_out, int out_size) {
    const float* pred = (const float*)d_in[0];
    const float* tgt  = (const float*)d_in[1];
    const int* Hp = (const int*)d_in[2];
    const int* Wp = (const int*)d_in[3];
    long n_pred = in_sizes[0];
    long n_tgt  = in_sizes[1];
    long n_cells = n_pred / ROW;
    int ntg = (int)(n_tgt / 5);

    int dense_nb = (int)((n_cells + (long)NT * UNROLL - 1) / ((long)NT * UNROLL));
    int tgt_nb = (ntg + WPB - 1) / WPB;

    loss_kernel<<<dense_nb + tgt_nb, NT>>>(pred, tgt, Hp, Wp, n_cells, ntg,
                                           dense_nb, (float*)d_out, out_size);
}